// round 8
// baseline (speedup 1.0000x reference)
#include <cuda_runtime.h>
#include <math.h>

// Problem constants
#define U 64
#define M 8192
#define D 64
#define CHUNKS 16                       // chunks for both kernels
#define SLOTS_PER_CHUNK (M / CHUNKS)    // 512

// k_scores TMA pipeline
#define SC_STAGE_SLOTS 32
#define SC_STAGE_BYTES (SC_STAGE_SLOTS * D * 4)        // 8192
#define SC_NSTAGES 4
#define SC_NITERS (SLOTS_PER_CHUNK / SC_STAGE_SLOTS)   // 16

// k_weighted TMA pipeline
#define STAGE_SLOTS 32
#define STAGE_BYTES (STAGE_SLOTS * D * 4)              // 8192
#define NSTAGES 4
#define NITERS (SLOTS_PER_CHUNK / STAGE_SLOTS)         // 16

// Output layout (float32, tuple concatenated):
//   outputs  [64,64]      at 0
//   weights  [64,8192]    at 4096
//   memories [64,8192,64] at 528384
#define OFF_OUTPUTS  0
#define OFF_WEIGHTS  (U * D)
#define OFF_MEMCOPY  (U * D + U * M)

// Scratch (device globals; no allocation)
__device__ float2 g_stats[U * CHUNKS];           // per-(unit,chunk) (max, sumexp)
__device__ float  g_partial[U * CHUNKS * D];     // per-(unit,chunk) partial outputs
__device__ int    g_cnt[U];                      // arrival counters (self-resetting)

// ---------------------------------------------------------------------------
// mbarrier / bulk-async helpers
// ---------------------------------------------------------------------------
__device__ __forceinline__ unsigned smem_u32(const void* p) {
    return (unsigned)__cvta_generic_to_shared(p);
}
__device__ __forceinline__ void mbar_init(unsigned a, unsigned cnt) {
    asm volatile("mbarrier.init.shared.b64 [%0], %1;" :: "r"(a), "r"(cnt) : "memory");
}
__device__ __forceinline__ void mbar_expect_tx(unsigned a, unsigned bytes) {
    asm volatile("mbarrier.arrive.expect_tx.shared.b64 _, [%0], %1;"
                 :: "r"(a), "r"(bytes) : "memory");
}
__device__ __forceinline__ void mbar_wait(unsigned a, unsigned parity) {
    asm volatile(
        "{\n\t.reg .pred p;\n\t"
        "WL_%=:\n\t"
        "mbarrier.try_wait.parity.acquire.cta.shared::cta.b64 p, [%0], %1, 0x989680;\n\t"
        "@!p bra WL_%=;\n\t}"
        :: "r"(a), "r"(parity) : "memory");
}
__device__ __forceinline__ void bulk_load(unsigned dst_smem, const void* src,
                                          unsigned bytes, unsigned mbar) {
    asm volatile(
        "cp.async.bulk.shared::cluster.global.mbarrier::complete_tx::bytes "
        "[%0], [%1], %2, [%3];"
        :: "r"(dst_smem), "l"(src), "r"(bytes), "r"(mbar) : "memory");
}

// ---------------------------------------------------------------------------
// Kernel 1: raw scores + online-softmax chunk stats, TMA-staged.
// Grid (16 chunks of 512 slots, 64 units), 256 threads.
// slot = tid>>3 (32 slots/stage), part = tid&7; each thread covers 2 float4s
// of its slot at rotated columns -> conflict-free LDS.128. 3-shuffle reduce.
// ---------------------------------------------------------------------------
__global__ void __launch_bounds__(256)
k_scores(const float* __restrict__ att,
         const float* __restrict__ atts,
         const int*   __restrict__ mask,
         const float* __restrict__ tmpr,
         float*       __restrict__ w_out)
{
    __shared__ __align__(128) float4 stg[SC_NSTAGES][SC_STAGE_SLOTS * 16]; // 32 KB
    __shared__ float2 sred[32];
    __shared__ __align__(8) unsigned long long mbar[SC_NSTAGES];

    int u     = blockIdx.y;
    int chunk = blockIdx.x;
    int m0    = chunk * SLOTS_PER_CHUNK;
    int tid   = threadIdx.x;
    int part  = tid & 7;
    int slotl = tid >> 3;                 // 0..31

    // Rotated column pair for this thread (bank-conflict-free per quarter-warp)
    int k0 = (part + slotl) & 7;
    int k1 = k0 + 8;

    const float4* qp = (const float4*)(att + (u << 6));
    float4 q0 = qp[k0];
    float4 q1 = qp[k1];
    float  inv_t = 1.0f / tmpr[u];

    const char* gsrc = (const char*)(atts + ((size_t)u << 19) + ((size_t)m0 << 6));
    float*      wrow = w_out + ((size_t)u << 13);
    const int*  mrow = mask  + ((size_t)u << 13);

    if (tid == 0) {
        #pragma unroll
        for (int i = 0; i < SC_NSTAGES; i++) mbar_init(smem_u32(&mbar[i]), 1);
    }
    __syncthreads();
    if (tid == 0) {
        #pragma unroll
        for (int p = 0; p < SC_NSTAGES; p++) {
            unsigned mb = smem_u32(&mbar[p]);
            mbar_expect_tx(mb, SC_STAGE_BYTES);
            bulk_load(smem_u32(&stg[p][0]), gsrc + (size_t)p * SC_STAGE_BYTES,
                      SC_STAGE_BYTES, mb);
        }
    }

    float mx = -3.4e38f;     // online stats (only meaningful on part==0)
    float se = 0.f;

    for (int s = 0; s < SC_NITERS; s++) {
        int buf = s & (SC_NSTAGES - 1);
        mbar_wait(smem_u32(&mbar[buf]), (s >> 2) & 1);

        const float4* row = &stg[buf][slotl * 16];
        float4 v0 = row[k0];
        float4 v1 = row[k1];
        float p = v0.x * q0.x + v0.y * q0.y + v0.z * q0.z + v0.w * q0.w
                + v1.x * q1.x + v1.y * q1.y + v1.z * q1.z + v1.w * q1.w;
        p += __shfl_xor_sync(0xffffffffu, p, 1);
        p += __shfl_xor_sync(0xffffffffu, p, 2);
        p += __shfl_xor_sync(0xffffffffu, p, 4);

        if (part == 0) {
            int m = m0 + s * SC_STAGE_SLOTS + slotl;
            if (__ldg(&mrow[m])) p = -1e9f;     // RandomMask before temperature
            p *= inv_t;
            __stcg(&wrow[m], p);                // raw score (normalized later)
            float nm = fmaxf(mx, p);
            se = se * __expf(mx - nm) + __expf(p - nm);
            mx = nm;
        }

        __syncthreads();      // all consumers done with buf
        if (tid == 0 && s + SC_NSTAGES < SC_NITERS) {
            unsigned mb = smem_u32(&mbar[buf]);
            mbar_expect_tx(mb, SC_STAGE_BYTES);
            bulk_load(smem_u32(&stg[buf][0]),
                      gsrc + (size_t)(s + SC_NSTAGES) * SC_STAGE_BYTES,
                      SC_STAGE_BYTES, mb);
        }
    }

    if (part == 0) sred[slotl] = make_float2(mx, se);
    __syncthreads();

    if (tid < 32) {
        float2 a = sred[tid];
        float m1 = a.x, s1 = a.y;
        #pragma unroll
        for (int o = 16; o > 0; o >>= 1) {
            float m2 = __shfl_xor_sync(0xffffffffu, m1, o);
            float s2 = __shfl_xor_sync(0xffffffffu, s1, o);
            float nm = fmaxf(m1, m2);
            s1 = s1 * __expf(m1 - nm) + s2 * __expf(m2 - nm);
            m1 = nm;
        }
        if (tid == 0)
            g_stats[u * CHUNKS + chunk] = make_float2(m1, s1);
    }
}

// ---------------------------------------------------------------------------
// Kernel 2: combine stats -> normalize -> weights; TMA-staged memories;
// fused copy + weighted sum; last-block-per-unit reduction -> outputs.
// (Unchanged from R5 except the 16-entry stats combine.)
// ---------------------------------------------------------------------------
__global__ void __launch_bounds__(256)
k_weighted(const float* __restrict__ mem,
           float*       __restrict__ w,        // raw in, norm out
           float*       __restrict__ mem_copy,
           float*       __restrict__ outputs)
{
    __shared__ __align__(128) float4 stage[NSTAGES][STAGE_SLOTS * 16]; // 32 KB
    __shared__ float  ws[SLOTS_PER_CHUNK];                             // 2 KB
    __shared__ float4 red[16][16];                                     // 4 KB
    __shared__ __align__(8) unsigned long long mbar[NSTAGES];
    __shared__ float2 stat;
    __shared__ int    is_last;

    int u     = blockIdx.y;
    int chunk = blockIdx.x;
    int m0    = chunk * SLOTS_PER_CHUNK;
    int tid   = threadIdx.x;

    // Warp 0: combine the 16 chunk stats (fixed order -> identical in all blocks)
    if (tid < 32) {
        const float2* st = &g_stats[u * CHUNKS];
        float2 a = (tid < CHUNKS) ? st[tid] : make_float2(-3.4e38f, 0.f);
        float mx = a.x;
        #pragma unroll
        for (int o = 16; o > 0; o >>= 1)
            mx = fmaxf(mx, __shfl_xor_sync(0xffffffffu, mx, o));
        float se = a.y * __expf(a.x - mx);
        #pragma unroll
        for (int o = 16; o > 0; o >>= 1)
            se += __shfl_xor_sync(0xffffffffu, se, o);
        if (tid == 0) stat = make_float2(mx, 1.0f / se);
    }
    if (tid == 0) {
        #pragma unroll
        for (int i = 0; i < NSTAGES; i++) mbar_init(smem_u32(&mbar[i]), 1);
    }
    __syncthreads();

    float mx      = stat.x;
    float inv_sum = stat.y;

    size_t base = ((size_t)u << 19) + ((size_t)m0 << 6);   // floats
    const char* gsrc = (const char*)(mem + base);

    if (tid == 0) {
        #pragma unroll
        for (int p = 0; p < NSTAGES; p++) {
            unsigned mb = smem_u32(&mbar[p]);
            mbar_expect_tx(mb, STAGE_BYTES);
            bulk_load(smem_u32(&stage[p][0]), gsrc + (size_t)p * STAGE_BYTES,
                      STAGE_BYTES, mb);
        }
    }

    // Normalize raw scores -> shared + weights output (overlaps with TMA)
    float* wrow = w + ((size_t)u << 13) + m0;
    {
        float w0 = __expf(wrow[tid]       - mx) * inv_sum;
        float w1 = __expf(wrow[tid + 256] - mx) * inv_sum;
        ws[tid]       = w0;
        ws[tid + 256] = w1;
        wrow[tid]       = w0;
        wrow[tid + 256] = w1;
    }
    __syncthreads();

    int lane = tid & 15;
    int r    = tid >> 4;
    float4* dst = (float4*)(mem_copy + base);

    float4 acc = make_float4(0.f, 0.f, 0.f, 0.f);
    for (int s = 0; s < NITERS; s++) {
        int buf = s & (NSTAGES - 1);
        mbar_wait(smem_u32(&mbar[buf]), (s >> 2) & 1);

        int mloc = s * STAGE_SLOTS;
        float4 v0 = stage[buf][r * 16 + lane];
        float4 v1 = stage[buf][(r + 16) * 16 + lane];
        __stcs(&dst[(size_t)(mloc + r) * 16 + lane], v0);
        __stcs(&dst[(size_t)(mloc + r + 16) * 16 + lane], v1);
        float w0 = ws[mloc + r];
        float w1 = ws[mloc + r + 16];
        acc.x = fmaf(w0, v0.x, fmaf(w1, v1.x, acc.x));
        acc.y = fmaf(w0, v0.y, fmaf(w1, v1.y, acc.y));
        acc.z = fmaf(w0, v0.z, fmaf(w1, v1.z, acc.z));
        acc.w = fmaf(w0, v0.w, fmaf(w1, v1.w, acc.w));

        __syncthreads();        // all consumers done with buf
        if (tid == 0 && s + NSTAGES < NITERS) {
            unsigned mb = smem_u32(&mbar[buf]);
            mbar_expect_tx(mb, STAGE_BYTES);
            bulk_load(smem_u32(&stage[buf][0]),
                      gsrc + (size_t)(s + NSTAGES) * STAGE_BYTES,
                      STAGE_BYTES, mb);
        }
    }

    red[r][lane] = acc;
    __syncthreads();
    if (r == 0) {
        float4 s = red[0][lane];
        #pragma unroll
        for (int j = 1; j < 16; j++) {
            s.x += red[j][lane].x;
            s.y += red[j][lane].y;
            s.z += red[j][lane].z;
            s.w += red[j][lane].w;
        }
        ((float4*)g_partial)[((size_t)u * CHUNKS + chunk) * 16 + lane] = s;
    }

    // Make this block's partial visible, then arrive on the unit counter.
    __threadfence();
    __syncthreads();
    if (tid == 0)
        is_last = (atomicAdd(&g_cnt[u], 1) == CHUNKS - 1) ? 1 : 0;
    __syncthreads();

    if (is_last) {
        __threadfence();
        if (tid < 16) {
            const float4* p = (const float4*)g_partial + (size_t)u * CHUNKS * 16;
            float4 s = make_float4(0.f, 0.f, 0.f, 0.f);
            #pragma unroll
            for (int c = 0; c < CHUNKS; c++) {
                float4 q = p[c * 16 + tid];
                s.x += q.x; s.y += q.y; s.z += q.z; s.w += q.w;
            }
            ((float4*)outputs)[u * 16 + tid] = s;
        }
        if (tid == 0) g_cnt[u] = 0;     // self-reset for next graph replay
    }
}

// ---------------------------------------------------------------------------
extern "C" void kernel_launch(void* const* d_in, const int* in_sizes, int n_in,
                              void* d_out, int out_size)
{
    const float* att  = (const float*)d_in[0];   // [64,64]
    const float* atts = (const float*)d_in[1];   // [64,8192,64]
    const float* mem  = (const float*)d_in[2];   // [64,8192,64]
    const float* tmpr = (const float*)d_in[3];   // [64,1]
    const int*   mask = (const int*)  d_in[4];   // [64,8192] bool->int32

    float* out      = (float*)d_out;
    float* outputs  = out + OFF_OUTPUTS;
    float* weights  = out + OFF_WEIGHTS;
    float* mem_copy = out + OFF_MEMCOPY;

    // 1) raw scores + softmax chunk stats (TMA-staged)
    {
        dim3 grid(CHUNKS, U);
        k_scores<<<grid, 256>>>(att, atts, mask, tmpr, weights);
    }
    // 2) normalize + TMA-staged copy/weighted-sum + final reduce
    {
        dim3 grid(CHUNKS, U);
        k_weighted<<<grid, 256>>>(mem, weights, mem_copy, outputs);
    }
}

// round 9
// speedup vs baseline: 1.0011x; 1.0011x over previous
#include <cuda_runtime.h>
#include <math.h>

// Problem constants
#define U 64
#define M 8192
#define D 64
#define CHUNKS 16                       // chunks for both kernels
#define SLOTS_PER_CHUNK (M / CHUNKS)    // 512

// TMA pipeline (both kernels): 64 slots = 16 KB per stage, 3 stages, 8 iters
#define STAGE_SLOTS 64
#define STAGE_BYTES (STAGE_SLOTS * D * 4)            // 16384
#define NSTAGES 3
#define NITERS (SLOTS_PER_CHUNK / STAGE_SLOTS)       // 8

// Output layout (float32, tuple concatenated):
//   outputs  [64,64]      at 0
//   weights  [64,8192]    at 4096
//   memories [64,8192,64] at 528384
#define OFF_OUTPUTS  0
#define OFF_WEIGHTS  (U * D)
#define OFF_MEMCOPY  (U * D + U * M)

// Scratch (device globals; no allocation)
__device__ float2 g_stats[U * CHUNKS];           // per-(unit,chunk) (max, sumexp)
__device__ float  g_partial[U * CHUNKS * D];     // per-(unit,chunk) partial outputs
__device__ int    g_cnt[U];                      // arrival counters (self-resetting)

// ---------------------------------------------------------------------------
// mbarrier / bulk-async helpers
// ---------------------------------------------------------------------------
__device__ __forceinline__ unsigned smem_u32(const void* p) {
    return (unsigned)__cvta_generic_to_shared(p);
}
__device__ __forceinline__ void mbar_init(unsigned a, unsigned cnt) {
    asm volatile("mbarrier.init.shared.b64 [%0], %1;" :: "r"(a), "r"(cnt) : "memory");
}
__device__ __forceinline__ void mbar_expect_tx(unsigned a, unsigned bytes) {
    asm volatile("mbarrier.arrive.expect_tx.shared.b64 _, [%0], %1;"
                 :: "r"(a), "r"(bytes) : "memory");
}
__device__ __forceinline__ void mbar_wait(unsigned a, unsigned parity) {
    asm volatile(
        "{\n\t.reg .pred p;\n\t"
        "WL_%=:\n\t"
        "mbarrier.try_wait.parity.acquire.cta.shared::cta.b64 p, [%0], %1, 0x989680;\n\t"
        "@!p bra WL_%=;\n\t}"
        :: "r"(a), "r"(parity) : "memory");
}
__device__ __forceinline__ void bulk_load(unsigned dst_smem, const void* src,
                                          unsigned bytes, unsigned mbar) {
    asm volatile(
        "cp.async.bulk.shared::cluster.global.mbarrier::complete_tx::bytes "
        "[%0], [%1], %2, [%3];"
        :: "r"(dst_smem), "l"(src), "r"(bytes), "r"(mbar) : "memory");
}

// ---------------------------------------------------------------------------
// Kernel 1: raw scores + online-softmax chunk stats, TMA-staged.
// Grid (16 chunks of 512 slots, 64 units), 256 threads.
// part = tid&7, slotl = tid>>3; each thread handles slots (slotl, slotl+32)
// per stage with rotated columns -> conflict-free LDS.128.
// ---------------------------------------------------------------------------
__global__ void __launch_bounds__(256)
k_scores(const float* __restrict__ att,
         const float* __restrict__ atts,
         const int*   __restrict__ mask,
         const float* __restrict__ tmpr,
         float*       __restrict__ w_out)
{
    __shared__ __align__(128) float4 stg[NSTAGES][STAGE_SLOTS * 16];  // 48 KB
    __shared__ int    msk[SLOTS_PER_CHUNK];                           // 2 KB
    __shared__ float2 sred[32];
    __shared__ __align__(8) unsigned long long mbar[NSTAGES];

    int u     = blockIdx.y;
    int chunk = blockIdx.x;
    int m0    = chunk * SLOTS_PER_CHUNK;
    int tid   = threadIdx.x;
    int part  = tid & 7;
    int slotl = tid >> 3;                 // 0..31

    int k0 = (part + slotl) & 7;          // rotated column pair
    int k1 = k0 + 8;

    const float4* qp = (const float4*)(att + (u << 6));
    float4 q0 = qp[k0];
    float4 q1 = qp[k1];
    float  inv_t = 1.0f / tmpr[u];

    const char* gsrc = (const char*)(atts + ((size_t)u << 19) + ((size_t)m0 << 6));
    float*      wrow = w_out + ((size_t)u << 13) + m0;
    const int*  mrow = mask  + ((size_t)u << 13) + m0;

    if (tid == 0) {
        #pragma unroll
        for (int i = 0; i < NSTAGES; i++) mbar_init(smem_u32(&mbar[i]), 1);
    }
    // Preload mask chunk into smem (coalesced, overlaps with nothing hot)
    msk[tid]       = mrow[tid];
    msk[tid + 256] = mrow[tid + 256];
    __syncthreads();

    if (tid == 0) {
        #pragma unroll
        for (int p = 0; p < NSTAGES; p++) {
            unsigned mb = smem_u32(&mbar[p]);
            mbar_expect_tx(mb, STAGE_BYTES);
            bulk_load(smem_u32(&stg[p][0]), gsrc + (size_t)p * STAGE_BYTES,
                      STAGE_BYTES, mb);
        }
    }

    float mx = -3.4e38f;     // online stats (meaningful on part==0)
    float se = 0.f;

    int buf = 0, ph = 0;
    for (int s = 0; s < NITERS; s++) {
        mbar_wait(smem_u32(&mbar[buf]), ph);

        const float4* rowA = &stg[buf][slotl * 16];
        const float4* rowB = &stg[buf][(slotl + 32) * 16];
        float4 a0 = rowA[k0], a1 = rowA[k1];
        float4 b0 = rowB[k0], b1 = rowB[k1];
        float pA = a0.x * q0.x + a0.y * q0.y + a0.z * q0.z + a0.w * q0.w
                 + a1.x * q1.x + a1.y * q1.y + a1.z * q1.z + a1.w * q1.w;
        float pB = b0.x * q0.x + b0.y * q0.y + b0.z * q0.z + b0.w * q0.w
                 + b1.x * q1.x + b1.y * q1.y + b1.z * q1.z + b1.w * q1.w;
        #pragma unroll
        for (int o = 1; o <= 4; o <<= 1) {
            pA += __shfl_xor_sync(0xffffffffu, pA, o);
            pB += __shfl_xor_sync(0xffffffffu, pB, o);
        }

        if (part == 0) {
            int mA = s * STAGE_SLOTS + slotl;
            int mB = mA + 32;
            if (msk[mA]) pA = -1e9f;            // RandomMask before temperature
            if (msk[mB]) pB = -1e9f;
            pA *= inv_t;
            pB *= inv_t;
            __stcg(&wrow[mA], pA);
            __stcg(&wrow[mB], pB);
            float nm = fmaxf(mx, fmaxf(pA, pB));
            se = se * __expf(mx - nm) + __expf(pA - nm) + __expf(pB - nm);
            mx = nm;
        }

        __syncthreads();      // all consumers done with buf
        if (tid == 0 && s + NSTAGES < NITERS) {
            unsigned mb = smem_u32(&mbar[buf]);
            mbar_expect_tx(mb, STAGE_BYTES);
            bulk_load(smem_u32(&stg[buf][0]),
                      gsrc + (size_t)(s + NSTAGES) * STAGE_BYTES,
                      STAGE_BYTES, mb);
        }
        if (++buf == NSTAGES) { buf = 0; ph ^= 1; }
    }

    if (part == 0) sred[slotl] = make_float2(mx, se);
    __syncthreads();

    if (tid < 32) {
        float2 a = sred[tid];
        float m1 = a.x, s1 = a.y;
        #pragma unroll
        for (int o = 16; o > 0; o >>= 1) {
            float m2 = __shfl_xor_sync(0xffffffffu, m1, o);
            float s2 = __shfl_xor_sync(0xffffffffu, s1, o);
            float nm = fmaxf(m1, m2);
            s1 = s1 * __expf(m1 - nm) + s2 * __expf(m2 - nm);
            m1 = nm;
        }
        if (tid == 0)
            g_stats[u * CHUNKS + chunk] = make_float2(m1, s1);
    }
}

// ---------------------------------------------------------------------------
// Kernel 2: combine stats -> normalize -> weights; TMA-staged memories
// (64-slot stages); fused copy + weighted sum; last-block reduction.
// 256 threads = 16 lanes x 16 row-groups; 4 slots/thread/stage.
// ---------------------------------------------------------------------------
__global__ void __launch_bounds__(256)
k_weighted(const float* __restrict__ mem,
           float*       __restrict__ w,        // raw in, norm out
           float*       __restrict__ mem_copy,
           float*       __restrict__ outputs)
{
    __shared__ __align__(128) float4 stage[NSTAGES][STAGE_SLOTS * 16]; // 48 KB
    __shared__ float  ws[SLOTS_PER_CHUNK];                             // 2 KB
    __shared__ float4 red[16][16];                                     // 4 KB
    __shared__ __align__(8) unsigned long long mbar[NSTAGES];
    __shared__ float2 stat;
    __shared__ int    is_last;

    int u     = blockIdx.y;
    int chunk = blockIdx.x;
    int m0    = chunk * SLOTS_PER_CHUNK;
    int tid   = threadIdx.x;

    // Warp 0: combine the 16 chunk stats (fixed order -> identical in all blocks)
    if (tid < 32) {
        const float2* st = &g_stats[u * CHUNKS];
        float2 a = (tid < CHUNKS) ? st[tid] : make_float2(-3.4e38f, 0.f);
        float mx = a.x;
        #pragma unroll
        for (int o = 16; o > 0; o >>= 1)
            mx = fmaxf(mx, __shfl_xor_sync(0xffffffffu, mx, o));
        float se = a.y * __expf(a.x - mx);
        #pragma unroll
        for (int o = 16; o > 0; o >>= 1)
            se += __shfl_xor_sync(0xffffffffu, se, o);
        if (tid == 0) stat = make_float2(mx, 1.0f / se);
    }
    if (tid == 0) {
        #pragma unroll
        for (int i = 0; i < NSTAGES; i++) mbar_init(smem_u32(&mbar[i]), 1);
    }
    __syncthreads();

    float mx      = stat.x;
    float inv_sum = stat.y;

    size_t base = ((size_t)u << 19) + ((size_t)m0 << 6);   // floats
    const char* gsrc = (const char*)(mem + base);

    if (tid == 0) {
        #pragma unroll
        for (int p = 0; p < NSTAGES; p++) {
            unsigned mb = smem_u32(&mbar[p]);
            mbar_expect_tx(mb, STAGE_BYTES);
            bulk_load(smem_u32(&stage[p][0]), gsrc + (size_t)p * STAGE_BYTES,
                      STAGE_BYTES, mb);
        }
    }

    // Normalize raw scores -> shared + weights output (overlaps with TMA)
    float* wrow = w + ((size_t)u << 13) + m0;
    {
        float w0 = __expf(wrow[tid]       - mx) * inv_sum;
        float w1 = __expf(wrow[tid + 256] - mx) * inv_sum;
        ws[tid]       = w0;
        ws[tid + 256] = w1;
        wrow[tid]       = w0;
        wrow[tid + 256] = w1;
    }
    __syncthreads();

    int lane = tid & 15;
    int r    = tid >> 4;
    float4* dst = (float4*)(mem_copy + base);

    float4 acc = make_float4(0.f, 0.f, 0.f, 0.f);
    int buf = 0, ph = 0;
    for (int s = 0; s < NITERS; s++) {
        mbar_wait(smem_u32(&mbar[buf]), ph);

        int mloc = s * STAGE_SLOTS;
        #pragma unroll
        for (int j = 0; j < 4; j++) {
            int sl = r + j * 16;
            float4 v = stage[buf][sl * 16 + lane];
            __stcs(&dst[(size_t)(mloc + sl) * 16 + lane], v);
            float wm = ws[mloc + sl];
            acc.x = fmaf(wm, v.x, acc.x);
            acc.y = fmaf(wm, v.y, acc.y);
            acc.z = fmaf(wm, v.z, acc.z);
            acc.w = fmaf(wm, v.w, acc.w);
        }

        __syncthreads();        // all consumers done with buf
        if (tid == 0 && s + NSTAGES < NITERS) {
            unsigned mb = smem_u32(&mbar[buf]);
            mbar_expect_tx(mb, STAGE_BYTES);
            bulk_load(smem_u32(&stage[buf][0]),
                      gsrc + (size_t)(s + NSTAGES) * STAGE_BYTES,
                      STAGE_BYTES, mb);
        }
        if (++buf == NSTAGES) { buf = 0; ph ^= 1; }
    }

    red[r][lane] = acc;
    __syncthreads();
    if (r == 0) {
        float4 s = red[0][lane];
        #pragma unroll
        for (int j = 1; j < 16; j++) {
            s.x += red[j][lane].x;
            s.y += red[j][lane].y;
            s.z += red[j][lane].z;
            s.w += red[j][lane].w;
        }
        ((float4*)g_partial)[((size_t)u * CHUNKS + chunk) * 16 + lane] = s;
    }

    // Make this block's partial visible, then arrive on the unit counter.
    __threadfence();
    __syncthreads();
    if (tid == 0)
        is_last = (atomicAdd(&g_cnt[u], 1) == CHUNKS - 1) ? 1 : 0;
    __syncthreads();

    if (is_last) {
        __threadfence();
        if (tid < 16) {
            const float4* p = (const float4*)g_partial + (size_t)u * CHUNKS * 16;
            float4 s = make_float4(0.f, 0.f, 0.f, 0.f);
            #pragma unroll
            for (int c = 0; c < CHUNKS; c++) {
                float4 q = p[c * 16 + tid];
                s.x += q.x; s.y += q.y; s.z += q.z; s.w += q.w;
            }
            ((float4*)outputs)[u * 16 + tid] = s;
        }
        if (tid == 0) g_cnt[u] = 0;     // self-reset for next graph replay
    }
}

// ---------------------------------------------------------------------------
extern "C" void kernel_launch(void* const* d_in, const int* in_sizes, int n_in,
                              void* d_out, int out_size)
{
    const float* att  = (const float*)d_in[0];   // [64,64]
    const float* atts = (const float*)d_in[1];   // [64,8192,64]
    const float* mem  = (const float*)d_in[2];   // [64,8192,64]
    const float* tmpr = (const float*)d_in[3];   // [64,1]
    const int*   mask = (const int*)  d_in[4];   // [64,8192] bool->int32

    float* out      = (float*)d_out;
    float* outputs  = out + OFF_OUTPUTS;
    float* weights  = out + OFF_WEIGHTS;
    float* mem_copy = out + OFF_MEMCOPY;

    // 1) raw scores + softmax chunk stats (TMA-staged)
    {
        dim3 grid(CHUNKS, U);
        k_scores<<<grid, 256>>>(att, atts, mask, tmpr, weights);
    }
    // 2) normalize + TMA-staged copy/weighted-sum + final reduce
    {
        dim3 grid(CHUNKS, U);
        k_weighted<<<grid, 256>>>(mem, weights, mem_copy, outputs);
    }
}

// round 10
// speedup vs baseline: 1.1349x; 1.1336x over previous
#include <cuda_runtime.h>
#include <math.h>

// Problem constants
#define U 64
#define M 8192
#define D 64
#define CHUNKS 8                        // chunks for both kernels -> 512 blocks
#define SLOTS_PER_CHUNK (M / CHUNKS)    // 1024

// k_scores TMA pipeline: 64 slots = 16 KB per stage, 3 stages, 16 iters
#define SC_STAGE_SLOTS 64
#define SC_STAGE_BYTES (SC_STAGE_SLOTS * D * 4)           // 16384
#define SC_NSTAGES 3
#define SC_NITERS (SLOTS_PER_CHUNK / SC_STAGE_SLOTS)      // 16

// k_weighted TMA pipeline: 32 slots = 8 KB per stage, 4 stages, 32 iters
#define STAGE_SLOTS 32
#define STAGE_BYTES (STAGE_SLOTS * D * 4)                 // 8192
#define NSTAGES 4
#define NITERS (SLOTS_PER_CHUNK / STAGE_SLOTS)            // 32

// Output layout (float32, tuple concatenated):
//   outputs  [64,64]      at 0
//   weights  [64,8192]    at 4096
//   memories [64,8192,64] at 528384
#define OFF_OUTPUTS  0
#define OFF_WEIGHTS  (U * D)
#define OFF_MEMCOPY  (U * D + U * M)

// Scratch (device globals; no allocation)
__device__ float2 g_stats[U * CHUNKS];           // per-(unit,chunk) (max, sumexp)
__device__ float  g_partial[U * CHUNKS * D];     // per-(unit,chunk) partial outputs
__device__ int    g_cnt[U];                      // arrival counters (self-resetting)

// ---------------------------------------------------------------------------
// mbarrier / bulk-async helpers
// ---------------------------------------------------------------------------
__device__ __forceinline__ unsigned smem_u32(const void* p) {
    return (unsigned)__cvta_generic_to_shared(p);
}
__device__ __forceinline__ void mbar_init(unsigned a, unsigned cnt) {
    asm volatile("mbarrier.init.shared.b64 [%0], %1;" :: "r"(a), "r"(cnt) : "memory");
}
__device__ __forceinline__ void mbar_expect_tx(unsigned a, unsigned bytes) {
    asm volatile("mbarrier.arrive.expect_tx.shared.b64 _, [%0], %1;"
                 :: "r"(a), "r"(bytes) : "memory");
}
__device__ __forceinline__ void mbar_wait(unsigned a, unsigned parity) {
    asm volatile(
        "{\n\t.reg .pred p;\n\t"
        "WL_%=:\n\t"
        "mbarrier.try_wait.parity.acquire.cta.shared::cta.b64 p, [%0], %1, 0x989680;\n\t"
        "@!p bra WL_%=;\n\t}"
        :: "r"(a), "r"(parity) : "memory");
}
__device__ __forceinline__ void bulk_load(unsigned dst_smem, const void* src,
                                          unsigned bytes, unsigned mbar) {
    asm volatile(
        "cp.async.bulk.shared::cluster.global.mbarrier::complete_tx::bytes "
        "[%0], [%1], %2, [%3];"
        :: "r"(dst_smem), "l"(src), "r"(bytes), "r"(mbar) : "memory");
}

// ---------------------------------------------------------------------------
// Kernel 1: raw scores + online-softmax chunk stats, TMA-staged.
// Grid (8 chunks of 1024 slots, 64 units) = 512 blocks -> single wave.
// part = tid&7, slotl = tid>>3; 2 slots/thread/stage, rotated columns ->
// conflict-free LDS.128; 3-shuffle reduce over 8 lanes.
// ---------------------------------------------------------------------------
__global__ void __launch_bounds__(256)
k_scores(const float* __restrict__ att,
         const float* __restrict__ atts,
         const int*   __restrict__ mask,
         const float* __restrict__ tmpr,
         float*       __restrict__ w_out)
{
    __shared__ __align__(128) float4 stg[SC_NSTAGES][SC_STAGE_SLOTS * 16]; // 48 KB
    __shared__ int    msk[SLOTS_PER_CHUNK];                                // 4 KB
    __shared__ float2 sred[32];
    __shared__ __align__(8) unsigned long long mbar[SC_NSTAGES];

    int u     = blockIdx.y;
    int chunk = blockIdx.x;
    int m0    = chunk * SLOTS_PER_CHUNK;
    int tid   = threadIdx.x;
    int part  = tid & 7;
    int slotl = tid >> 3;                 // 0..31

    int k0 = (part + slotl) & 7;          // rotated column pair
    int k1 = k0 + 8;

    const float4* qp = (const float4*)(att + (u << 6));
    float4 q0 = qp[k0];
    float4 q1 = qp[k1];
    float  inv_t = 1.0f / tmpr[u];

    const char* gsrc = (const char*)(atts + ((size_t)u << 19) + ((size_t)m0 << 6));
    float*      wrow = w_out + ((size_t)u << 13) + m0;
    const int*  mrow = mask  + ((size_t)u << 13) + m0;

    if (tid == 0) {
        #pragma unroll
        for (int i = 0; i < SC_NSTAGES; i++) mbar_init(smem_u32(&mbar[i]), 1);
    }
    // Preload mask chunk into smem (coalesced)
    #pragma unroll
    for (int j = 0; j < SLOTS_PER_CHUNK / 256; j++)
        msk[tid + j * 256] = mrow[tid + j * 256];
    __syncthreads();

    if (tid == 0) {
        #pragma unroll
        for (int p = 0; p < SC_NSTAGES; p++) {
            unsigned mb = smem_u32(&mbar[p]);
            mbar_expect_tx(mb, SC_STAGE_BYTES);
            bulk_load(smem_u32(&stg[p][0]), gsrc + (size_t)p * SC_STAGE_BYTES,
                      SC_STAGE_BYTES, mb);
        }
    }

    float mx = -3.4e38f;     // online stats (meaningful on part==0)
    float se = 0.f;

    int buf = 0, ph = 0;
    for (int s = 0; s < SC_NITERS; s++) {
        mbar_wait(smem_u32(&mbar[buf]), ph);

        const float4* rowA = &stg[buf][slotl * 16];
        const float4* rowB = &stg[buf][(slotl + 32) * 16];
        float4 a0 = rowA[k0], a1 = rowA[k1];
        float4 b0 = rowB[k0], b1 = rowB[k1];
        float pA = a0.x * q0.x + a0.y * q0.y + a0.z * q0.z + a0.w * q0.w
                 + a1.x * q1.x + a1.y * q1.y + a1.z * q1.z + a1.w * q1.w;
        float pB = b0.x * q0.x + b0.y * q0.y + b0.z * q0.z + b0.w * q0.w
                 + b1.x * q1.x + b1.y * q1.y + b1.z * q1.z + b1.w * q1.w;
        #pragma unroll
        for (int o = 1; o <= 4; o <<= 1) {
            pA += __shfl_xor_sync(0xffffffffu, pA, o);
            pB += __shfl_xor_sync(0xffffffffu, pB, o);
        }

        if (part == 0) {
            int mA = s * SC_STAGE_SLOTS + slotl;
            int mB = mA + 32;
            if (msk[mA]) pA = -1e9f;            // RandomMask before temperature
            if (msk[mB]) pB = -1e9f;
            pA *= inv_t;
            pB *= inv_t;
            __stcg(&wrow[mA], pA);
            __stcg(&wrow[mB], pB);
            float nm = fmaxf(mx, fmaxf(pA, pB));
            se = se * __expf(mx - nm) + __expf(pA - nm) + __expf(pB - nm);
            mx = nm;
        }

        __syncthreads();      // all consumers done with buf
        if (tid == 0 && s + SC_NSTAGES < SC_NITERS) {
            unsigned mb = smem_u32(&mbar[buf]);
            mbar_expect_tx(mb, SC_STAGE_BYTES);
            bulk_load(smem_u32(&stg[buf][0]),
                      gsrc + (size_t)(s + SC_NSTAGES) * SC_STAGE_BYTES,
                      SC_STAGE_BYTES, mb);
        }
        if (++buf == SC_NSTAGES) { buf = 0; ph ^= 1; }
    }

    if (part == 0) sred[slotl] = make_float2(mx, se);
    __syncthreads();

    if (tid < 32) {
        float2 a = sred[tid];
        float m1 = a.x, s1 = a.y;
        #pragma unroll
        for (int o = 16; o > 0; o >>= 1) {
            float m2 = __shfl_xor_sync(0xffffffffu, m1, o);
            float s2 = __shfl_xor_sync(0xffffffffu, s1, o);
            float nm = fmaxf(m1, m2);
            s1 = s1 * __expf(m1 - nm) + s2 * __expf(m2 - nm);
            m1 = nm;
        }
        if (tid == 0)
            g_stats[u * CHUNKS + chunk] = make_float2(m1, s1);
    }
}

// ---------------------------------------------------------------------------
// Kernel 2: combine stats -> normalize -> weights; TMA-staged memories
// (32-slot x 4 stages = proven R5 shape); fused STG copy + weighted sum;
// last-block-per-unit reduction. Grid (8, 64) = 512 blocks -> single wave.
// ---------------------------------------------------------------------------
__global__ void __launch_bounds__(256)
k_weighted(const float* __restrict__ mem,
           float*       __restrict__ w,        // raw in, norm out
           float*       __restrict__ mem_copy,
           float*       __restrict__ outputs)
{
    __shared__ __align__(128) float4 stage[NSTAGES][STAGE_SLOTS * 16]; // 32 KB
    __shared__ float  ws[SLOTS_PER_CHUNK];                             // 4 KB
    __shared__ float4 red[16][16];                                     // 4 KB
    __shared__ __align__(8) unsigned long long mbar[NSTAGES];
    __shared__ float2 stat;
    __shared__ int    is_last;

    int u     = blockIdx.y;
    int chunk = blockIdx.x;
    int m0    = chunk * SLOTS_PER_CHUNK;
    int tid   = threadIdx.x;

    // Warp 0: combine the 8 chunk stats (fixed order -> identical in all blocks)
    if (tid < 32) {
        const float2* st = &g_stats[u * CHUNKS];
        float2 a = (tid < CHUNKS) ? st[tid] : make_float2(-3.4e38f, 0.f);
        float mx = a.x;
        #pragma unroll
        for (int o = 16; o > 0; o >>= 1)
            mx = fmaxf(mx, __shfl_xor_sync(0xffffffffu, mx, o));
        float se = a.y * __expf(a.x - mx);
        #pragma unroll
        for (int o = 16; o > 0; o >>= 1)
            se += __shfl_xor_sync(0xffffffffu, se, o);
        if (tid == 0) stat = make_float2(mx, 1.0f / se);
    }
    if (tid == 0) {
        #pragma unroll
        for (int i = 0; i < NSTAGES; i++) mbar_init(smem_u32(&mbar[i]), 1);
    }
    __syncthreads();

    float mx      = stat.x;
    float inv_sum = stat.y;

    size_t base = ((size_t)u << 19) + ((size_t)m0 << 6);   // floats
    const char* gsrc = (const char*)(mem + base);

    if (tid == 0) {
        #pragma unroll
        for (int p = 0; p < NSTAGES; p++) {
            unsigned mb = smem_u32(&mbar[p]);
            mbar_expect_tx(mb, STAGE_BYTES);
            bulk_load(smem_u32(&stage[p][0]), gsrc + (size_t)p * STAGE_BYTES,
                      STAGE_BYTES, mb);
        }
    }

    // Normalize raw scores -> shared + weights output (overlaps with TMA)
    float* wrow = w + ((size_t)u << 13) + m0;
    #pragma unroll
    for (int j = 0; j < SLOTS_PER_CHUNK / 256; j++) {
        float wv = __expf(wrow[tid + j * 256] - mx) * inv_sum;
        ws[tid + j * 256]   = wv;
        wrow[tid + j * 256] = wv;
    }
    __syncthreads();

    int lane = tid & 15;
    int r    = tid >> 4;
    float4* dst = (float4*)(mem_copy + base);

    float4 acc = make_float4(0.f, 0.f, 0.f, 0.f);
    int buf = 0, ph = 0;
    for (int s = 0; s < NITERS; s++) {
        mbar_wait(smem_u32(&mbar[buf]), ph);

        int mloc = s * STAGE_SLOTS;
        float4 v0 = stage[buf][r * 16 + lane];
        float4 v1 = stage[buf][(r + 16) * 16 + lane];
        __stcs(&dst[(size_t)(mloc + r) * 16 + lane], v0);
        __stcs(&dst[(size_t)(mloc + r + 16) * 16 + lane], v1);
        float w0 = ws[mloc + r];
        float w1 = ws[mloc + r + 16];
        acc.x = fmaf(w0, v0.x, fmaf(w1, v1.x, acc.x));
        acc.y = fmaf(w0, v0.y, fmaf(w1, v1.y, acc.y));
        acc.z = fmaf(w0, v0.z, fmaf(w1, v1.z, acc.z));
        acc.w = fmaf(w0, v0.w, fmaf(w1, v1.w, acc.w));

        __syncthreads();        // all consumers done with buf
        if (tid == 0 && s + NSTAGES < NITERS) {
            unsigned mb = smem_u32(&mbar[buf]);
            mbar_expect_tx(mb, STAGE_BYTES);
            bulk_load(smem_u32(&stage[buf][0]),
                      gsrc + (size_t)(s + NSTAGES) * STAGE_BYTES,
                      STAGE_BYTES, mb);
        }
        if (++buf == NSTAGES) { buf = 0; ph ^= 1; }
    }

    red[r][lane] = acc;
    __syncthreads();
    if (r == 0) {
        float4 s = red[0][lane];
        #pragma unroll
        for (int j = 1; j < 16; j++) {
            s.x += red[j][lane].x;
            s.y += red[j][lane].y;
            s.z += red[j][lane].z;
            s.w += red[j][lane].w;
        }
        ((float4*)g_partial)[((size_t)u * CHUNKS + chunk) * 16 + lane] = s;
    }

    // Make this block's partial visible, then arrive on the unit counter.
    __threadfence();
    __syncthreads();
    if (tid == 0)
        is_last = (atomicAdd(&g_cnt[u], 1) == CHUNKS - 1) ? 1 : 0;
    __syncthreads();

    if (is_last) {
        __threadfence();
        if (tid < 16) {
            const float4* p = (const float4*)g_partial + (size_t)u * CHUNKS * 16;
            float4 s = make_float4(0.f, 0.f, 0.f, 0.f);
            #pragma unroll
            for (int c = 0; c < CHUNKS; c++) {
                float4 q = p[c * 16 + tid];
                s.x += q.x; s.y += q.y; s.z += q.z; s.w += q.w;
            }
            ((float4*)outputs)[u * 16 + tid] = s;
        }
        if (tid == 0) g_cnt[u] = 0;     // self-reset for next graph replay
    }
}

// ---------------------------------------------------------------------------
extern "C" void kernel_launch(void* const* d_in, const int* in_sizes, int n_in,
                              void* d_out, int out_size)
{
    const float* att  = (const float*)d_in[0];   // [64,64]
    const float* atts = (const float*)d_in[1];   // [64,8192,64]
    const float* mem  = (const float*)d_in[2];   // [64,8192,64]
    const float* tmpr = (const float*)d_in[3];   // [64,1]
    const int*   mask = (const int*)  d_in[4];   // [64,8192] bool->int32

    float* out      = (float*)d_out;
    float* outputs  = out + OFF_OUTPUTS;
    float* weights  = out + OFF_WEIGHTS;
    float* mem_copy = out + OFF_MEMCOPY;

    // 1) raw scores + softmax chunk stats (TMA-staged, single wave)
    {
        dim3 grid(CHUNKS, U);
        k_scores<<<grid, 256>>>(att, atts, mask, tmpr, weights);
    }
    // 2) normalize + TMA-staged copy/weighted-sum + final reduce (single wave)
    {
        dim3 grid(CHUNKS, U);
        k_weighted<<<grid, 256>>>(mem, weights, mem_copy, outputs);
    }
}